// round 15
// baseline (speedup 1.0000x reference)
#include <cuda_runtime.h>
#include <cuda_fp16.h>
#include <cstdint>

// ---------------------------------------------------------------------------
// RNN-T joint network (sm_103 legacy tensor path, fp16 mma everywhere):
//   XT = x@W_tr + b_tr   [1600,256] fp32 out, fp16 tensor math
//   YP = y@W_pr + b_pr   [400,256]  fp32 out, fp16 tensor math
//   Zh = fp16(tanh(XT[bt] + YP[b,u]))  [160000, 256]
//   out= Zh @ Wh + b_cls [160000,1024]
// Joint GEMM v2: persistent 296 CTAs, 256 thr, 8 warps of 64x32 (2Mx4N),
// B resident in smem, A 3-stage cp.async ring. 16 warps/SM for latency hiding.
// ---------------------------------------------------------------------------

#define B_  4
#define T_  400
#define U_  100
#define DTR 768
#define DPR 640
#define DJ  256
#define V_  1024
#define M_TOTAL (B_ * T_ * U_)   // 160000

__device__ float  g_XT[(size_t)B_ * T_ * DJ];
__device__ float  g_YP[(size_t)B_ * U_ * DJ];
__device__ __half g_Zh[(size_t)M_TOTAL * DJ];    // 82 MB
__device__ __half g_Wh[(size_t)V_ * DJ];         // fp16(W_cls^T)  [V][DJ]
__device__ __half g_WtrT[(size_t)DJ * DTR];      // fp16(W_tr^T)   [256][768]
__device__ __half g_WprT[(size_t)DJ * DPR];      // fp16(W_pr^T)   [256][640]

__device__ __forceinline__ float fast_tanh(float x) {
    float r;
    asm("tanh.approx.f32 %0, %1;" : "=f"(r) : "f"(x));
    return r;
}

__device__ __forceinline__ void mma_f16(float* c, const uint32_t* a, const uint32_t* b) {
    asm volatile(
        "mma.sync.aligned.m16n8k16.row.col.f32.f16.f16.f32 "
        "{%0,%1,%2,%3}, {%4,%5,%6,%7}, {%8,%9}, {%0,%1,%2,%3};\n"
        : "+f"(c[0]), "+f"(c[1]), "+f"(c[2]), "+f"(c[3])
        : "r"(a[0]), "r"(a[1]), "r"(a[2]), "r"(a[3]), "r"(b[0]), "r"(b[1]));
}

__device__ __forceinline__ void ldsm_x4(uint32_t& r0, uint32_t& r1, uint32_t& r2,
                                        uint32_t& r3, uint32_t addr) {
    asm volatile("ldmatrix.sync.aligned.m8n8.x4.shared.b16 {%0,%1,%2,%3}, [%4];"
                 : "=r"(r0), "=r"(r1), "=r"(r2), "=r"(r3) : "r"(addr));
}

__device__ __forceinline__ void ldsm_x2(uint32_t& r0, uint32_t& r1, uint32_t addr) {
    asm volatile("ldmatrix.sync.aligned.m8n8.x2.shared.b16 {%0,%1}, [%2];"
                 : "=r"(r0), "=r"(r1) : "r"(addr));
}

__device__ __forceinline__ uint32_t smem_u32(const void* p) {
    uint32_t a;
    asm("{ .reg .u64 t; cvta.to.shared.u64 t, %1; cvt.u32.u64 %0, t; }" : "=r"(a) : "l"(p));
    return a;
}

// ---------------------------------------------------------------------------
// Stage 0 (merged): all three weight transposes+fp16 in one launch.
// ---------------------------------------------------------------------------
__global__ __launch_bounds__(256)
void prep_weights(const float* __restrict__ Wcls, const float* __restrict__ Wtr,
                  const float* __restrict__ Wpr, __half* __restrict__ Wh,
                  __half* __restrict__ WtrT, __half* __restrict__ WprT) {
    __shared__ float t[32][33];
    const int idx = blockIdx.x;
    const float* W;
    __half* D;
    int srcN, dstK, n0, k0;
    if (idx < 256) {
        W = Wcls; D = Wh; srcN = V_; dstK = DJ;
        n0 = (idx & 31) * 32; k0 = (idx >> 5) * 32;
    } else if (idx < 448) {
        int i = idx - 256;
        W = Wtr; D = WtrT; srcN = DJ; dstK = DTR;
        n0 = (i & 7) * 32; k0 = (i >> 3) * 32;
    } else {
        int i = idx - 448;
        W = Wpr; D = WprT; srcN = DJ; dstK = DPR;
        n0 = (i & 7) * 32; k0 = (i >> 3) * 32;
    }
    int tx = threadIdx.x, ty = threadIdx.y;   // (32, 8)
#pragma unroll
    for (int i = 0; i < 32; i += 8)
        t[ty + i][tx] = W[(size_t)(k0 + ty + i) * srcN + n0 + tx];
    __syncthreads();
#pragma unroll
    for (int i = 0; i < 32; i += 8)
        D[(size_t)(n0 + ty + i) * dstK + k0 + tx] = __float2half_rn(t[tx][ty + i]);
}

// ---------------------------------------------------------------------------
// Stage 1 v3 (fused XT + YP): fp16 tensor GEMM, fp32-out, all-B prefetched.
// (unchanged from R13)
// ---------------------------------------------------------------------------
#define IG_B_CH 4096                        // 32 * 128
#define IG_A_CH 2048                        // 16 * 128
#define IG_MAXCH 12
#define IG_SMEM (IG_MAXCH * (IG_B_CH + IG_A_CH))   // 73728

__global__ __launch_bounds__(128)
void in_gemm_f16(const float* __restrict__ x, const float* __restrict__ y,
                 const __half* __restrict__ WtrT, const __half* __restrict__ WprT,
                 const float* __restrict__ btr, const float* __restrict__ bpr,
                 float* __restrict__ XT, float* __restrict__ YP) {
    extern __shared__ char sm[];
    const uint32_t smbase = smem_u32(sm);
    const uint32_t abase = smbase + IG_MAXCH * IG_B_CH;

    const int blk = blockIdx.x;
    const bool isY = blk >= 800;
    const int bidx = isY ? blk - 800 : blk;
    const float* A = isY ? y : x;
    const __half* Wt = isY ? WprT : WtrT;
    const float* bias = isY ? bpr : btr;
    float* C = isY ? YP : XT;
    const int m0 = (bidx >> 3) * 16;
    const int n0 = (bidx & 7) * 32;
    const int K = isY ? DPR : DTR;
    const int nch = K / 64;                  // 12 or 10

    const int tid = threadIdx.x;
    const int lane = tid & 31, w = tid >> 5;
    const int gid = lane >> 2, tig = lane & 3;

    {
        const int b_row = tid >> 2;
        const int b_c0 = (tid & 3) * 2;
        const __half* b_src = Wt + (size_t)(n0 + b_row) * K;
        const uint32_t b_dst = smbase + (uint32_t)b_row * 128;
        const uint32_t brx = (uint32_t)(b_row & 7);
#pragma unroll 4
        for (int c = 0; c < nch; c++) {
#pragma unroll
            for (int i = 0; i < 2; i++) {
                uint32_t ch = (uint32_t)(b_c0 + i);
                asm volatile("cp.async.cg.shared.global [%0], [%1], 16;"
                             :: "r"(b_dst + (uint32_t)c * IG_B_CH + ((ch ^ brx) << 4)),
                                "l"(b_src + c * 64 + ch * 8));
            }
            asm volatile("cp.async.commit_group;" ::: "memory");
        }
        for (int c = nch; c < IG_MAXCH; c++)
            asm volatile("cp.async.commit_group;" ::: "memory");
    }

    {
        const int a_row = tid >> 3;
        const int a_ch = tid & 7;
        const float* a_srcp = A + (size_t)(m0 + a_row) * K + a_ch * 8;
        char* a_dstp = sm + (IG_MAXCH * IG_B_CH) + a_row * 128 +
                       (((uint32_t)a_ch ^ (uint32_t)(a_row & 7)) << 4);
#pragma unroll 4
        for (int c = 0; c < nch; c++) {
            float4 v0 = *(const float4*)(a_srcp + c * 64);
            float4 v1 = *(const float4*)(a_srcp + c * 64 + 4);
            __half2 h0 = __floats2half2_rn(v0.x, v0.y);
            __half2 h1 = __floats2half2_rn(v0.z, v0.w);
            __half2 h2 = __floats2half2_rn(v1.x, v1.y);
            __half2 h3 = __floats2half2_rn(v1.z, v1.w);
            uint4 pk;
            pk.x = *reinterpret_cast<uint32_t*>(&h0);
            pk.y = *reinterpret_cast<uint32_t*>(&h1);
            pk.z = *reinterpret_cast<uint32_t*>(&h2);
            pk.w = *reinterpret_cast<uint32_t*>(&h3);
            *reinterpret_cast<uint4*>(a_dstp + c * IG_A_CH) = pk;
        }
    }

    const int l8 = lane & 7, j = lane >> 3;
    const uint32_t rowlowA = (uint32_t)(((j & 1) << 3) + l8);
    const uint32_t cbitA = (uint32_t)(j >> 1);
    const uint32_t xorvA = (uint32_t)l8;
    const uint32_t aBase = abase + rowlowA * 128;
    const int l16 = lane & 15;
    const uint32_t jb = (uint32_t)(l16 >> 3);
    const uint32_t rowB = (uint32_t)(w * 8 + (l16 & 7));
    const uint32_t xorvB = (uint32_t)(l16 & 7);
    const uint32_t bBase = smbase + rowB * 128;

    float acc[4];
    acc[0] = acc[1] = acc[2] = acc[3] = 0.f;

#define IG_CHUNK(c) \
    if ((c) < nch) { \
        asm volatile("cp.async.wait_group %0;" :: "n"(IG_MAXCH - 1 - (c)) : "memory"); \
        __syncthreads(); \
        _Pragma("unroll") \
        for (int ks = 0; ks < 4; ks++) { \
            uint32_t a[4], b[2]; \
            ldsm_x4(a[0], a[1], a[2], a[3], \
                    aBase + (c) * IG_A_CH + \
                    ((((uint32_t)(ks << 1) + cbitA) ^ xorvA) << 4)); \
            ldsm_x2(b[0], b[1], \
                    bBase + (c) * IG_B_CH + \
                    ((((uint32_t)(ks << 1) + jb) ^ xorvB) << 4)); \
            mma_f16(acc, a, b); \
        } \
    }

    IG_CHUNK(0);  IG_CHUNK(1);  IG_CHUNK(2);  IG_CHUNK(3);
    IG_CHUNK(4);  IG_CHUNK(5);  IG_CHUNK(6);  IG_CHUNK(7);
    IG_CHUNK(8);  IG_CHUNK(9);  IG_CHUNK(10); IG_CHUNK(11);
#undef IG_CHUNK

    {
        int cidx = n0 + w * 8 + 2 * tig;
        float bv0 = __ldg(bias + cidx);
        float bv1 = __ldg(bias + cidx + 1);
        float* r0p = C + (size_t)(m0 + gid) * DJ + cidx;
        float* r1p = C + (size_t)(m0 + gid + 8) * DJ + cidx;
        r0p[0] = acc[0] + bv0;
        r0p[1] = acc[1] + bv1;
        r1p[0] = acc[2] + bv0;
        r1p[1] = acc[3] + bv1;
    }
}

// ---------------------------------------------------------------------------
// Stage 2: Zh = fp16(tanh_hw(XT[bt,:] + YP[b*U+u,:]))  (unchanged)
// ---------------------------------------------------------------------------
__global__ __launch_bounds__(256)
void z_tanh_kernel(const float* __restrict__ XT, const float* __restrict__ YP,
                   __half* __restrict__ Z) {
    const int bt = blockIdx.x;          // 0..1599
    const int b = bt / T_;
    const int tid = threadIdx.x;

    const int phase = tid >> 6;
    const int c4 = (tid & 63) * 4;
    float4 xv = *(const float4*)(XT + (size_t)bt * DJ + c4);

    __half* zrow = Z + (size_t)bt * U_ * DJ + c4;
    const float* yb = YP + (size_t)b * U_ * DJ + c4;

#pragma unroll 5
    for (int u = phase; u < U_; u += 4) {
        float4 yv = *(const float4*)(yb + (size_t)u * DJ);
        __half2 h0 = __floats2half2_rn(fast_tanh(xv.x + yv.x), fast_tanh(xv.y + yv.y));
        __half2 h1 = __floats2half2_rn(fast_tanh(xv.z + yv.z), fast_tanh(xv.w + yv.w));
        uint2 pk;
        pk.x = *reinterpret_cast<uint32_t*>(&h0);
        pk.y = *reinterpret_cast<uint32_t*>(&h1);
        *reinterpret_cast<uint2*>(zrow + (size_t)u * DJ) = pk;
    }
}

// ---------------------------------------------------------------------------
// Stage 3 v2: out = Zh @ Wh^T + b_cls, persistent CTAs.
// 296 CTAs (2/SM), 256 threads, 8 warps of 64x32 (2M x 4N).
// B resident (512B rows, chunk^=(row&7)); A 3-stage ring of 16KB chunks.
// 16 warps/SM (4/SMSP) to hide ldsm->mma latency.
// ---------------------------------------------------------------------------
#define BM 128
#define BN 128
#define BKH 64
#define ROWB 128
#define A_STAGE_BYTES (BM * ROWB)               // 16384
#define NSTAGES 3
#define B_BYTES (BN * DJ * 2)                   // 65536
#define B_OFF (NSTAGES * A_STAGE_BYTES)         // 49152
#define JSMEM (B_OFF + B_BYTES)                 // 114688
#define NCHUNKS (DJ / BKH)                      // 4
#define MGROUPS 37
#define MTILES (M_TOTAL / BM)                   // 1250
#define NJCTAS (8 * MGROUPS)                    // 296

__global__ __launch_bounds__(256, 2)
void joint_gemm_f16(const __half* __restrict__ Z, const __half* __restrict__ Wh,
                    const float* __restrict__ bias, float* __restrict__ out) {
    extern __shared__ char sm[];
    const uint32_t smbase = smem_u32(sm);
    const uint32_t bbase = smbase + B_OFF;

    const int K = DJ;
    const int N = V_;

    const int n0 = (blockIdx.x & 7) * BN;
    const int mgroup = blockIdx.x >> 3;
    const int tid = threadIdx.x;
    const int lane = tid & 31, w = tid >> 5;
    const int warpM = w & 1, warpN = w >> 1;    // 2 x 4
    const int wm0 = warpM * 64, wn0 = warpN * 32;
    const int gid = lane >> 2, tig = lane & 3;

    const int l8 = lane & 7, j = lane >> 3;
    const uint32_t rowlow = (uint32_t)(((j & 1) << 3) + l8);
    const uint32_t cbit = (uint32_t)(j >> 1);
    const uint32_t xorv = (uint32_t)l8;
    const uint32_t aRow = ((uint32_t)wm0 + rowlow) * ROWB;          // + fm*16*ROWB
    const uint32_t bRow = bbase + ((uint32_t)wn0 + rowlow) * 512;   // + p*16*512

    // bias: 8 values per thread (fn<4)
    float bv[4][2];
#pragma unroll
    for (int fn = 0; fn < 4; fn++) {
        int cidx = n0 + wn0 + fn * 8 + 2 * tig;
        bv[fn][0] = bias[cidx];
        bv[fn][1] = bias[cidx + 1];
    }

    // one-time B load: 128 rows x 512B, 2 threads/row, 16 chunks each
    {
        int r = tid >> 1;
        int c0 = (tid & 1) * 16;
        const __half* src = Wh + (size_t)(n0 + r) * K + c0 * 8;
        uint32_t dbase = bbase + (uint32_t)r * 512;
        uint32_t rx = (uint32_t)(r & 7);
#pragma unroll
        for (int ch = 0; ch < 16; ch++) {
            uint32_t d = dbase + (((uint32_t)(c0 + ch) ^ rx) << 4);
            asm volatile("cp.async.cg.shared.global [%0], [%1], 16;"
                         :: "r"(d), "l"(src + ch * 8));
        }
        asm volatile("cp.async.commit_group;" ::: "memory");
    }

    // A streaming: 128 rows x 128B per chunk; 2 threads/row, 4 chunks each
    const int lrow = tid >> 1;          // 0..127
    const int lch0 = (tid & 1) * 4;     // 4 x 16B chunks

#define LOAD_A(mt, c, s) do { \
    uint32_t _sb = smbase + (uint32_t)(s) * A_STAGE_BYTES + (uint32_t)lrow * ROWB; \
    const __half* _a = Z + (size_t)((mt) * BM + lrow) * K + (c) * BKH + lch0 * 8; \
    uint32_t _rx = (uint32_t)(lrow & 7); \
    _Pragma("unroll") \
    for (int i = 0; i < 4; i++) { \
        uint32_t _d = _sb + (((uint32_t)(lch0 + i) ^ _rx) << 4); \
        asm volatile("cp.async.cg.shared.global [%0], [%1], 16;" \
                     :: "r"(_d), "l"(_a + i * 8)); \
    } \
    asm volatile("cp.async.commit_group;" ::: "memory"); \
} while (0)

    int lt = mgroup;
    int lc = 0;
    int ls = 0;
#define ADV_LOAD() do { \
    if (++lc == NCHUNKS) { lc = 0; lt += MGROUPS; if (lt >= MTILES) lt = -1; } \
    ls = (ls + 1 == NSTAGES) ? 0 : ls + 1; \
} while (0)

    LOAD_A(lt, lc, ls); ADV_LOAD();
    LOAD_A(lt, lc, ls); ADV_LOAD();

    int cs = 0;

#pragma unroll 1
    for (int t = mgroup; t < MTILES; t += MGROUPS) {
        const int m0 = t * BM;
        const bool lastTile = (t + MGROUPS >= MTILES);

        float acc[4][4][4];
#pragma unroll
        for (int fm = 0; fm < 4; fm++)
#pragma unroll
            for (int fn = 0; fn < 4; fn++)
#pragma unroll
                for (int r = 0; r < 4; r++) acc[fm][fn][r] = 0.f;

#pragma unroll
        for (int c = 0; c < NCHUNKS; c++) {
            if (lastTile && c == NCHUNKS - 1)
                asm volatile("cp.async.wait_group 0;" ::: "memory");
            else
                asm volatile("cp.async.wait_group 1;" ::: "memory");
            __syncthreads();
            if (lt >= 0) { LOAD_A(lt, lc, ls); ADV_LOAD(); }

            const uint32_t aB = smbase + (uint32_t)cs * A_STAGE_BYTES + aRow;
            cs = (cs + 1 == NSTAGES) ? 0 : cs + 1;
#pragma unroll
            for (int ks = 0; ks < 4; ks++) {
                const uint32_t aCh = (((uint32_t)(ks << 1) + cbit) ^ xorv) << 4;
                const uint32_t bCh = (((uint32_t)(c * 8 + (ks << 1)) + cbit) ^ xorv) << 4;
                uint32_t a[4][4], b[4][2];
#pragma unroll
                for (int fm = 0; fm < 4; fm++)
                    ldsm_x4(a[fm][0], a[fm][1], a[fm][2], a[fm][3],
                            aB + (uint32_t)fm * (16 * ROWB) + aCh);
#pragma unroll
                for (int p = 0; p < 2; p++) {
                    uint32_t r0, r1, r2, r3;
                    ldsm_x4(r0, r1, r2, r3, bRow + (uint32_t)p * (16 * 512) + bCh);
                    b[2 * p][0] = r0;
                    b[2 * p + 1][0] = r1;
                    b[2 * p][1] = r2;
                    b[2 * p + 1][1] = r3;
                }
#pragma unroll
                for (int fm = 0; fm < 4; fm++)
#pragma unroll
                    for (int fn = 0; fn < 4; fn++) mma_f16(acc[fm][fn], a[fm], b[fn]);
            }
        }

        // epilogue
#pragma unroll
        for (int fm = 0; fm < 4; fm++) {
            int r0 = m0 + wm0 + fm * 16 + gid;
#pragma unroll
            for (int fn = 0; fn < 4; fn++) {
                int cidx = n0 + wn0 + fn * 8 + 2 * tig;
                float2 v0 = make_float2(acc[fm][fn][0] + bv[fn][0],
                                        acc[fm][fn][1] + bv[fn][1]);
                float2 v1 = make_float2(acc[fm][fn][2] + bv[fn][0],
                                        acc[fm][fn][3] + bv[fn][1]);
                *(float2*)(out + (size_t)r0 * N + cidx) = v0;
                *(float2*)(out + (size_t)(r0 + 8) * N + cidx) = v1;
            }
        }
    }
#undef LOAD_A
#undef ADV_LOAD
}

// ---------------------------------------------------------------------------
extern "C" void kernel_launch(void* const* d_in, const int* in_sizes, int n_in,
                              void* d_out, int out_size) {
    const float* x     = (const float*)d_in[0];
    const float* y     = (const float*)d_in[1];
    const float* W_tr  = (const float*)d_in[2];
    const float* b_tr  = (const float*)d_in[3];
    const float* W_pr  = (const float*)d_in[4];
    const float* b_pr  = (const float*)d_in[5];
    const float* W_cls = (const float*)d_in[6];
    const float* b_cls = (const float*)d_in[7];
    float* out = (float*)d_out;

    void *pXT, *pYP, *pZh, *pWh, *pWtrT, *pWprT;
    cudaGetSymbolAddress(&pXT, g_XT);
    cudaGetSymbolAddress(&pYP, g_YP);
    cudaGetSymbolAddress(&pZh, g_Zh);
    cudaGetSymbolAddress(&pWh, g_Wh);
    cudaGetSymbolAddress(&pWtrT, g_WtrT);
    cudaGetSymbolAddress(&pWprT, g_WprT);

    // stage 0: all weight preps in one launch
    prep_weights<<<608, dim3(32, 8)>>>(W_cls, W_tr, W_pr, (__half*)pWh,
                                       (__half*)pWtrT, (__half*)pWprT);

    // stage 1: XT and YP
    {
        cudaFuncSetAttribute(in_gemm_f16, cudaFuncAttributeMaxDynamicSharedMemorySize,
                             IG_SMEM);
        in_gemm_f16<<<1000, 128, IG_SMEM>>>(x, y, (const __half*)pWtrT,
                                            (const __half*)pWprT, b_tr, b_pr,
                                            (float*)pXT, (float*)pYP);
    }
    // stage 2
    z_tanh_kernel<<<B_ * T_, 256>>>((const float*)pXT, (const float*)pYP, (__half*)pZh);
    // stage 3 (persistent, 256 threads)
    {
        cudaFuncSetAttribute(joint_gemm_f16, cudaFuncAttributeMaxDynamicSharedMemorySize,
                             JSMEM);
        joint_gemm_f16<<<NJCTAS, 256, JSMEM>>>((const __half*)pZh, (const __half*)pWh,
                                               b_cls, out);
    }
}

// round 16
// speedup vs baseline: 1.1119x; 1.1119x over previous
#include <cuda_runtime.h>
#include <cuda_fp16.h>
#include <cstdint>

// ---------------------------------------------------------------------------
// RNN-T joint network (sm_103 legacy tensor path, fp16 mma everywhere):
//   XT = x@W_tr + b_tr   [1600,256] fp32 out, fp16 tensor math
//   YP = y@W_pr + b_pr   [400,256]  fp32 out, fp16 tensor math
//   Zh = fp16(tanh(XT[bt] + YP[b,u]))  [160000, 256]
//   out= Zh @ Wh + b_cls [160000,1024]
// Joint GEMM: R13 config (proven fastest: 288us, at legacy HMMA pipe floor):
// persistent 296 CTAs, 128 thr, 4 warps of 64x64, B resident, 3-stage A ring.
// Stage-1 v4: 32mx32n XT tiles (halved B L2 traffic), all-B-upfront prefetch.
// ---------------------------------------------------------------------------

#define B_  4
#define T_  400
#define U_  100
#define DTR 768
#define DPR 640
#define DJ  256
#define V_  1024
#define M_TOTAL (B_ * T_ * U_)   // 160000

__device__ float  g_XT[(size_t)B_ * T_ * DJ];
__device__ float  g_YP[(size_t)B_ * U_ * DJ];
__device__ __half g_Zh[(size_t)M_TOTAL * DJ];    // 82 MB
__device__ __half g_Wh[(size_t)V_ * DJ];         // fp16(W_cls^T)  [V][DJ]
__device__ __half g_WtrT[(size_t)DJ * DTR];      // fp16(W_tr^T)   [256][768]
__device__ __half g_WprT[(size_t)DJ * DPR];      // fp16(W_pr^T)   [256][640]

__device__ __forceinline__ float fast_tanh(float x) {
    float r;
    asm("tanh.approx.f32 %0, %1;" : "=f"(r) : "f"(x));
    return r;
}

__device__ __forceinline__ void mma_f16(float* c, const uint32_t* a, const uint32_t* b) {
    asm volatile(
        "mma.sync.aligned.m16n8k16.row.col.f32.f16.f16.f32 "
        "{%0,%1,%2,%3}, {%4,%5,%6,%7}, {%8,%9}, {%0,%1,%2,%3};\n"
        : "+f"(c[0]), "+f"(c[1]), "+f"(c[2]), "+f"(c[3])
        : "r"(a[0]), "r"(a[1]), "r"(a[2]), "r"(a[3]), "r"(b[0]), "r"(b[1]));
}

__device__ __forceinline__ void ldsm_x4(uint32_t& r0, uint32_t& r1, uint32_t& r2,
                                        uint32_t& r3, uint32_t addr) {
    asm volatile("ldmatrix.sync.aligned.m8n8.x4.shared.b16 {%0,%1,%2,%3}, [%4];"
                 : "=r"(r0), "=r"(r1), "=r"(r2), "=r"(r3) : "r"(addr));
}

__device__ __forceinline__ void ldsm_x2(uint32_t& r0, uint32_t& r1, uint32_t addr) {
    asm volatile("ldmatrix.sync.aligned.m8n8.x2.shared.b16 {%0,%1}, [%2];"
                 : "=r"(r0), "=r"(r1) : "r"(addr));
}

__device__ __forceinline__ uint32_t smem_u32(const void* p) {
    uint32_t a;
    asm("{ .reg .u64 t; cvta.to.shared.u64 t, %1; cvt.u32.u64 %0, t; }" : "=r"(a) : "l"(p));
    return a;
}

// ---------------------------------------------------------------------------
// Stage 0 (merged): all three weight transposes+fp16 in one launch.
// ---------------------------------------------------------------------------
__global__ __launch_bounds__(256)
void prep_weights(const float* __restrict__ Wcls, const float* __restrict__ Wtr,
                  const float* __restrict__ Wpr, __half* __restrict__ Wh,
                  __half* __restrict__ WtrT, __half* __restrict__ WprT) {
    __shared__ float t[32][33];
    const int idx = blockIdx.x;
    const float* W;
    __half* D;
    int srcN, dstK, n0, k0;
    if (idx < 256) {
        W = Wcls; D = Wh; srcN = V_; dstK = DJ;
        n0 = (idx & 31) * 32; k0 = (idx >> 5) * 32;
    } else if (idx < 448) {
        int i = idx - 256;
        W = Wtr; D = WtrT; srcN = DJ; dstK = DTR;
        n0 = (i & 7) * 32; k0 = (i >> 3) * 32;
    } else {
        int i = idx - 448;
        W = Wpr; D = WprT; srcN = DJ; dstK = DPR;
        n0 = (i & 7) * 32; k0 = (i >> 3) * 32;
    }
    int tx = threadIdx.x, ty = threadIdx.y;   // (32, 8)
#pragma unroll
    for (int i = 0; i < 32; i += 8)
        t[ty + i][tx] = W[(size_t)(k0 + ty + i) * srcN + n0 + tx];
    __syncthreads();
#pragma unroll
    for (int i = 0; i < 32; i += 8)
        D[(size_t)(n0 + ty + i) * dstK + k0 + tx] = __float2half_rn(t[tx][ty + i]);
}

// ---------------------------------------------------------------------------
// Stage 1 v4 (fused XT + YP): fp16 tensor GEMM, fp32-out, all-B prefetched.
// Grid 600, 128 threads:
//   blk 0..399:   XT  32m x 32n  (m-tile = blk>>3, n-slice = blk&7, K=768)
//   blk 400..599: YP  16m x 32n  (K=640)
// Smem: 12 chunks x (B 32nx128B + A 32mx128B) = 96KB. B prefetch issued as
// 12 commit-groups up front (padded), A converted fp32->fp16 into smem.
// Main loop: wait_group(const) + sync + ldsm + mma only.
// Accumulation order per element (c asc, ks asc) -> bitwise-identical.
// ---------------------------------------------------------------------------
#define IG_B_CH 4096                        // 32n * 128B
#define IG_A_CH 4096                        // 32m * 128B
#define IG_MAXCH 12
#define IG_SMEM (IG_MAXCH * (IG_B_CH + IG_A_CH))   // 98304

__global__ __launch_bounds__(128)
void in_gemm_f16(const float* __restrict__ x, const float* __restrict__ y,
                 const __half* __restrict__ WtrT, const __half* __restrict__ WprT,
                 const float* __restrict__ btr, const float* __restrict__ bpr,
                 float* __restrict__ XT, float* __restrict__ YP) {
    extern __shared__ char sm[];
    const uint32_t smbase = smem_u32(sm);
    const uint32_t abase = smbase + IG_MAXCH * IG_B_CH;

    const int blk = blockIdx.x;
    const bool isY = blk >= 400;
    const int bidx = isY ? blk - 400 : blk;
    const float* A = isY ? y : x;
    const __half* Wt = isY ? WprT : WtrT;
    const float* bias = isY ? bpr : btr;
    float* C = isY ? YP : XT;
    const int n0 = (bidx & 7) * 32;
    const int m0 = isY ? (bidx >> 3) * 16 : (bidx >> 3) * 32;
    const int mrows = isY ? 16 : 32;
    const int nfm = isY ? 1 : 2;
    const int K = isY ? DPR : DTR;
    const int nch = K / 64;                  // 10 or 12

    const int tid = threadIdx.x;
    const int lane = tid & 31, w = tid >> 5;
    const int gid = lane >> 2, tig = lane & 3;

    // ---- B prefetch: thread t -> row t>>2 (0..31), chunks (t&3)*2, +1 ----
    {
        const int b_row = tid >> 2;
        const int b_c0 = (tid & 3) * 2;
        const __half* b_src = Wt + (size_t)(n0 + b_row) * K;
        const uint32_t b_dst = smbase + (uint32_t)b_row * 128;
        const uint32_t brx = (uint32_t)(b_row & 7);
#pragma unroll 4
        for (int c = 0; c < nch; c++) {
#pragma unroll
            for (int i = 0; i < 2; i++) {
                uint32_t ch = (uint32_t)(b_c0 + i);
                asm volatile("cp.async.cg.shared.global [%0], [%1], 16;"
                             :: "r"(b_dst + (uint32_t)c * IG_B_CH + ((ch ^ brx) << 4)),
                                "l"(b_src + c * 64 + ch * 8));
            }
            asm volatile("cp.async.commit_group;" ::: "memory");
        }
        for (int c = nch; c < IG_MAXCH; c++)
            asm volatile("cp.async.commit_group;" ::: "memory");   // empty groups
    }

    // ---- A convert: thread t -> row t>>2 (0..31), chunks (t&3)*2, +1 ----
    {
        const int a_row = tid >> 2;
        const int a_c0 = (tid & 3) * 2;
        if (a_row < mrows) {
            const float* a_srcp = A + (size_t)(m0 + a_row) * K;
            char* a_dstp = sm + (IG_MAXCH * IG_B_CH) + a_row * 128;
            const uint32_t arx = (uint32_t)(a_row & 7);
#pragma unroll 4
            for (int c = 0; c < nch; c++) {
#pragma unroll
                for (int i = 0; i < 2; i++) {
                    int ch = a_c0 + i;
                    float4 v0 = *(const float4*)(a_srcp + c * 64 + ch * 8);
                    float4 v1 = *(const float4*)(a_srcp + c * 64 + ch * 8 + 4);
                    __half2 h0 = __floats2half2_rn(v0.x, v0.y);
                    __half2 h1 = __floats2half2_rn(v0.z, v0.w);
                    __half2 h2 = __floats2half2_rn(v1.x, v1.y);
                    __half2 h3 = __floats2half2_rn(v1.z, v1.w);
                    uint4 pk;
                    pk.x = *reinterpret_cast<uint32_t*>(&h0);
                    pk.y = *reinterpret_cast<uint32_t*>(&h1);
                    pk.z = *reinterpret_cast<uint32_t*>(&h2);
                    pk.w = *reinterpret_cast<uint32_t*>(&h3);
                    *reinterpret_cast<uint4*>(
                        a_dstp + c * IG_A_CH + (((uint32_t)ch ^ arx) << 4)) = pk;
                }
            }
        }
    }

    // ---- fragment lane mappings ----
    const int l8 = lane & 7, j = lane >> 3;
    const uint32_t rowlowA = (uint32_t)(((j & 1) << 3) + l8);
    const uint32_t cbitA = (uint32_t)(j >> 1);
    const uint32_t xorvA = (uint32_t)l8;
    const uint32_t aBase = abase + rowlowA * 128;
    const int l16 = lane & 15;
    const uint32_t jb = (uint32_t)(l16 >> 3);
    const uint32_t rowB = (uint32_t)(w * 8 + (l16 & 7));
    const uint32_t xorvB = (uint32_t)(l16 & 7);
    const uint32_t bBase = smbase + rowB * 128;

    float acc[2][4];
#pragma unroll
    for (int fm = 0; fm < 2; fm++)
#pragma unroll
        for (int r = 0; r < 4; r++) acc[fm][r] = 0.f;

#define IG_CHUNK(c) \
    if ((c) < nch) { \
        asm volatile("cp.async.wait_group %0;" :: "n"(IG_MAXCH - 1 - (c)) : "memory"); \
        __syncthreads(); \
        _Pragma("unroll") \
        for (int ks = 0; ks < 4; ks++) { \
            const uint32_t aCh = (((uint32_t)(ks << 1) + cbitA) ^ xorvA) << 4; \
            const uint32_t bCh = (((uint32_t)(ks << 1) + jb) ^ xorvB) << 4; \
            uint32_t a0[4], b[2]; \
            ldsm_x4(a0[0], a0[1], a0[2], a0[3], aBase + (c) * IG_A_CH + aCh); \
            ldsm_x2(b[0], b[1], bBase + (c) * IG_B_CH + bCh); \
            mma_f16(acc[0], a0, b); \
            if (nfm == 2) { \
                uint32_t a1[4]; \
                ldsm_x4(a1[0], a1[1], a1[2], a1[3], \
                        aBase + (c) * IG_A_CH + 16 * 128 + aCh); \
                mma_f16(acc[1], a1, b); \
            } \
        } \
    }

    IG_CHUNK(0);  IG_CHUNK(1);  IG_CHUNK(2);  IG_CHUNK(3);
    IG_CHUNK(4);  IG_CHUNK(5);  IG_CHUNK(6);  IG_CHUNK(7);
    IG_CHUNK(8);  IG_CHUNK(9);  IG_CHUNK(10); IG_CHUNK(11);
#undef IG_CHUNK

    // epilogue: bias + fp32 store (warp w owns n [w*8, w*8+8))
    {
        int cidx = n0 + w * 8 + 2 * tig;
        float bv0 = __ldg(bias + cidx);
        float bv1 = __ldg(bias + cidx + 1);
#pragma unroll
        for (int fm = 0; fm < 2; fm++) {
            if (fm < nfm) {
                float* r0p = C + (size_t)(m0 + fm * 16 + gid) * DJ + cidx;
                float* r1p = C + (size_t)(m0 + fm * 16 + gid + 8) * DJ + cidx;
                r0p[0] = acc[fm][0] + bv0;
                r0p[1] = acc[fm][1] + bv1;
                r1p[0] = acc[fm][2] + bv0;
                r1p[1] = acc[fm][3] + bv1;
            }
        }
    }
}

// ---------------------------------------------------------------------------
// Stage 2: Zh = fp16(tanh_hw(XT[bt,:] + YP[b*U+u,:]))  (unchanged)
// ---------------------------------------------------------------------------
__global__ __launch_bounds__(256)
void z_tanh_kernel(const float* __restrict__ XT, const float* __restrict__ YP,
                   __half* __restrict__ Z) {
    const int bt = blockIdx.x;          // 0..1599
    const int b = bt / T_;
    const int tid = threadIdx.x;

    const int phase = tid >> 6;
    const int c4 = (tid & 63) * 4;
    float4 xv = *(const float4*)(XT + (size_t)bt * DJ + c4);

    __half* zrow = Z + (size_t)bt * U_ * DJ + c4;
    const float* yb = YP + (size_t)b * U_ * DJ + c4;

#pragma unroll 5
    for (int u = phase; u < U_; u += 4) {
        float4 yv = *(const float4*)(yb + (size_t)u * DJ);
        __half2 h0 = __floats2half2_rn(fast_tanh(xv.x + yv.x), fast_tanh(xv.y + yv.y));
        __half2 h1 = __floats2half2_rn(fast_tanh(xv.z + yv.z), fast_tanh(xv.w + yv.w));
        uint2 pk;
        pk.x = *reinterpret_cast<uint32_t*>(&h0);
        pk.y = *reinterpret_cast<uint32_t*>(&h1);
        *reinterpret_cast<uint2*>(zrow + (size_t)u * DJ) = pk;
    }
}

// ---------------------------------------------------------------------------
// Stage 3: out = Zh @ Wh^T + b_cls, persistent CTAs.
// R13 config (proven 288us, legacy HMMA pipe floor): 296 CTAs, 128 threads,
// 4 warps of 64x64 (2M x 2N). B resident; A 3-stage cp.async ring.
// ---------------------------------------------------------------------------
#define BM 128
#define BN 128
#define BKH 64
#define ROWB 128
#define A_STAGE_BYTES (BM * ROWB)               // 16384
#define NSTAGES 3
#define B_BYTES (BN * DJ * 2)                   // 65536
#define B_OFF (NSTAGES * A_STAGE_BYTES)         // 49152
#define JSMEM (B_OFF + B_BYTES)                 // 114688
#define NCHUNKS (DJ / BKH)                      // 4
#define MGROUPS 37
#define MTILES (M_TOTAL / BM)                   // 1250
#define NJCTAS (8 * MGROUPS)                    // 296

__global__ __launch_bounds__(128, 2)
void joint_gemm_f16(const __half* __restrict__ Z, const __half* __restrict__ Wh,
                    const float* __restrict__ bias, float* __restrict__ out) {
    extern __shared__ char sm[];
    const uint32_t smbase = smem_u32(sm);
    const uint32_t bbase = smbase + B_OFF;

    const int K = DJ;
    const int N = V_;

    const int n0 = (blockIdx.x & 7) * BN;
    const int mgroup = blockIdx.x >> 3;
    const int tid = threadIdx.x;
    const int lane = tid & 31, w = tid >> 5;
    const int warpM = w & 1, warpN = w >> 1;
    const int wm0 = warpM * 64, wn0 = warpN * 64;
    const int gid = lane >> 2, tig = lane & 3;

    const int l8 = lane & 7, j = lane >> 3;
    const uint32_t rowlow = (uint32_t)(((j & 1) << 3) + l8);
    const uint32_t cbit = (uint32_t)(j >> 1);
    const uint32_t xorv = (uint32_t)l8;
    const uint32_t aRow = ((uint32_t)wm0 + rowlow) * ROWB;
    const uint32_t bRow = bbase + ((uint32_t)wn0 + rowlow) * 512;

    float bv[8][2];
#pragma unroll
    for (int fn = 0; fn < 8; fn++) {
        int cidx = n0 + wn0 + fn * 8 + 2 * tig;
        bv[fn][0] = bias[cidx];
        bv[fn][1] = bias[cidx + 1];
    }

    {
        int r = tid;
        const __half* src = Wh + (size_t)(n0 + r) * K;
        uint32_t dbase = bbase + (uint32_t)r * 512;
        uint32_t rx = (uint32_t)(r & 7);
#pragma unroll
        for (int ch = 0; ch < 32; ch++) {
            uint32_t d = dbase + (((uint32_t)ch ^ rx) << 4);
            asm volatile("cp.async.cg.shared.global [%0], [%1], 16;"
                         :: "r"(d), "l"(src + ch * 8));
        }
        asm volatile("cp.async.commit_group;" ::: "memory");
    }

    const int lrow = tid >> 3;
    const int lchunk = tid & 7;

#define LOAD_A(mt, c, s) do { \
    uint32_t _sb = smbase + (uint32_t)(s) * A_STAGE_BYTES; \
    _Pragma("unroll") \
    for (int p = 0; p < 8; p++) { \
        int _r = lrow + p * 16; \
        uint32_t _d = _sb + (uint32_t)_r * ROWB + \
                      ((uint32_t)(lchunk ^ (_r & 7)) << 4); \
        const __half* _a = Z + (size_t)((mt) * BM + _r) * K + (c) * BKH + lchunk * 8; \
        asm volatile("cp.async.cg.shared.global [%0], [%1], 16;" \
                     :: "r"(_d), "l"(_a)); \
    } \
    asm volatile("cp.async.commit_group;" ::: "memory"); \
} while (0)

    int lt = mgroup;
    int lc = 0;
    int ls = 0;
#define ADV_LOAD() do { \
    if (++lc == NCHUNKS) { lc = 0; lt += MGROUPS; if (lt >= MTILES) lt = -1; } \
    ls = (ls + 1 == NSTAGES) ? 0 : ls + 1; \
} while (0)

    LOAD_A(lt, lc, ls); ADV_LOAD();
    LOAD_A(lt, lc, ls); ADV_LOAD();

    int cs = 0;

#pragma unroll 1
    for (int t = mgroup; t < MTILES; t += MGROUPS) {
        const int m0 = t * BM;
        const bool lastTile = (t + MGROUPS >= MTILES);

        float acc[4][8][4];
#pragma unroll
        for (int fm = 0; fm < 4; fm++)
#pragma unroll
            for (int fn = 0; fn < 8; fn++)
#pragma unroll
                for (int r = 0; r < 4; r++) acc[fm][fn][r] = 0.f;

#pragma unroll
        for (int c = 0; c < NCHUNKS; c++) {
            if (lastTile && c == NCHUNKS - 1)
                asm volatile("cp.async.wait_group 0;" ::: "memory");
            else
                asm volatile("cp.async.wait_group 1;" ::: "memory");
            __syncthreads();
            if (lt >= 0) { LOAD_A(lt, lc, ls); ADV_LOAD(); }

            const uint32_t aB = smbase + (uint32_t)cs * A_STAGE_BYTES + aRow;
            cs = (cs + 1 == NSTAGES) ? 0 : cs + 1;
#pragma unroll
            for (int ks = 0; ks < 4; ks++) {
                const uint32_t aCh = (((uint32_t)(ks << 1) + cbit) ^ xorv) << 4;
                const uint32_t bCh = (((uint32_t)(c * 8 + (ks << 1)) + cbit) ^ xorv) << 4;
                uint32_t a[4][4], b[8][2];
#pragma unroll
                for (int fm = 0; fm < 4; fm++)
                    ldsm_x4(a[fm][0], a[fm][1], a[fm][2], a[fm][3],
                            aB + (uint32_t)fm * (16 * ROWB) + aCh);
#pragma unroll
                for (int p = 0; p < 4; p++) {
                    uint32_t r0, r1, r2, r3;
                    ldsm_x4(r0, r1, r2, r3, bRow + (uint32_t)p * (16 * 512) + bCh);
                    b[2 * p][0] = r0;
                    b[2 * p + 1][0] = r1;
                    b[2 * p][1] = r2;
                    b[2 * p + 1][1] = r3;
                }
#pragma unroll
                for (int fm = 0; fm < 4; fm++)
#pragma unroll
                    for (int fn = 0; fn < 8; fn++) mma_f16(acc[fm][fn], a[fm], b[fn]);
            }
        }

#pragma unroll
        for (int fm = 0; fm < 4; fm++) {
            int r0 = m0 + wm0 + fm * 16 + gid;
#pragma unroll
            for (int fn = 0; fn < 8; fn++) {
                int cidx = n0 + wn0 + fn * 8 + 2 * tig;
                float2 v0 = make_float2(acc[fm][fn][0] + bv[fn][0],
                                        acc[fm][fn][1] + bv[fn][1]);
                float2 v1 = make_float2(acc[fm][fn][2] + bv[fn][0],
                                        acc[fm][fn][3] + bv[fn][1]);
                *(float2*)(out + (size_t)r0 * N + cidx) = v0;
                *(float2*)(out + (size_t)(r0 + 8) * N + cidx) = v1;
            }
        }
    }
#undef LOAD_A
#undef ADV_LOAD
}

// ---------------------------------------------------------------------------
extern "C" void kernel_launch(void* const* d_in, const int* in_sizes, int n_in,
                              void* d_out, int out_size) {
    const float* x     = (const float*)d_in[0];
    const float* y     = (const float*)d_in[1];
    const float* W_tr  = (const float*)d_in[2];
    const float* b_tr  = (const float*)d_in[3];
    const float* W_pr  = (const float*)d_in[4];
    const float* b_pr  = (const float*)d_in[5];
    const float* W_cls = (const float*)d_in[6];
    const float* b_cls = (const float*)d_in[7];
    float* out = (float*)d_out;

    void *pXT, *pYP, *pZh, *pWh, *pWtrT, *pWprT;
    cudaGetSymbolAddress(&pXT, g_XT);
    cudaGetSymbolAddress(&pYP, g_YP);
    cudaGetSymbolAddress(&pZh, g_Zh);
    cudaGetSymbolAddress(&pWh, g_Wh);
    cudaGetSymbolAddress(&pWtrT, g_WtrT);
    cudaGetSymbolAddress(&pWprT, g_WprT);

    // stage 0: all weight preps in one launch
    prep_weights<<<608, dim3(32, 8)>>>(W_cls, W_tr, W_pr, (__half*)pWh,
                                       (__half*)pWtrT, (__half*)pWprT);

    // stage 1: XT and YP (fused, fp16 tensor, all-B prefetch, 32m XT tiles)
    {
        cudaFuncSetAttribute(in_gemm_f16, cudaFuncAttributeMaxDynamicSharedMemorySize,
                             IG_SMEM);
        in_gemm_f16<<<600, 128, IG_SMEM>>>(x, y, (const __half*)pWtrT,
                                           (const __half*)pWprT, b_tr, b_pr,
                                           (float*)pXT, (float*)pYP);
    }
    // stage 2
    z_tanh_kernel<<<B_ * T_, 256>>>((const float*)pXT, (const float*)pYP, (__half*)pZh);
    // stage 3 (persistent, R13 config)
    {
        cudaFuncSetAttribute(joint_gemm_f16, cudaFuncAttributeMaxDynamicSharedMemorySize,
                             JSMEM);
        joint_gemm_f16<<<NJCTAS, 128, JSMEM>>>((const __half*)pZh, (const __half*)pWh,
                                               b_cls, out);
    }
}